// round 2
// baseline (speedup 1.0000x reference)
#include <cuda_runtime.h>
#include <cuda_bf16.h>
#include <math_constants.h>

#define MAXN 20000
#define MAXE 320000
#define MAXT (MAXE + MAXN)

// ---------------- scratch (device globals; no allocation) ----------------
__device__ float g_h1[MAXN * 256];
__device__ float g_out1[MAXN * 256];
__device__ float g_as1[MAXN * 4];
__device__ float g_ad1[MAXN * 4];
__device__ float g_h2[MAXN * 21];
__device__ float g_as2[MAXN];
__device__ float g_ad2[MAXN];
__device__ int   g_cnt[MAXN];
__device__ int   g_off[MAXN + 1];
__device__ int   g_cur[MAXN];
__device__ int   g_csr[MAXT];

__device__ __forceinline__ float leaky(float v) {
    return v > 0.f ? v : 0.2f * v;
}

// ---------------- layer1 GEMM + alpha reductions: one block per node ----------------
__global__ void k_gemm1(const float* __restrict__ x, const float* __restrict__ W1,
                        const float* __restrict__ asrc, const float* __restrict__ adst,
                        int N) {
    int n = blockIdx.x;
    int c = threadIdx.x;  // 0..255
    __shared__ float xs[3];
    __shared__ float red_s[8], red_d[8];
    if (c < 3) xs[c] = x[n * 3 + c];
    __syncthreads();
    float h = fmaf(xs[0], W1[c], fmaf(xs[1], W1[256 + c], xs[2] * W1[512 + c]));
    g_h1[n * 256 + c] = h;
    float ps = h * asrc[c];
    float pd = h * adst[c];
#pragma unroll
    for (int d = 16; d; d >>= 1) {
        ps += __shfl_xor_sync(0xFFFFFFFFu, ps, d);
        pd += __shfl_xor_sync(0xFFFFFFFFu, pd, d);
    }
    int w = c >> 5;
    if ((c & 31) == 0) { red_s[w] = ps; red_d[w] = pd; }
    __syncthreads();
    if (c < 4) {
        g_as1[n * 4 + c] = red_s[2 * c] + red_s[2 * c + 1];
        g_ad1[n * 4 + c] = red_d[2 * c] + red_d[2 * c + 1];
    }
}

// ---------------- CSR build ----------------
__global__ void k_zero(int N) {
    int i = blockIdx.x * blockDim.x + threadIdx.x;
    if (i < N) g_cnt[i] = 0;
}

__global__ void k_count(const int* __restrict__ ei, int E, int N) {
    int i = blockIdx.x * blockDim.x + threadIdx.x;
    if (i >= E + N) return;
    int dst = (i < E) ? ei[E + i] : (i - E);
    atomicAdd(&g_cnt[dst], 1);
}

// single-block scan: g_off = exclusive-scan prefix (off[0]=0, off[i+1]=off[i]+cnt[i]),
// also initializes g_cur[i] = off[i].
__global__ void k_scan(int n) {
    __shared__ int sh[1024];
    __shared__ int carry_s;
    int tid = threadIdx.x;
    if (tid == 0) { carry_s = 0; g_off[0] = 0; }
    __syncthreads();
    for (int base = 0; base < n; base += 1024) {
        int i = base + tid;
        int v = (i < n) ? g_cnt[i] : 0;
        sh[tid] = v;
        __syncthreads();
#pragma unroll
        for (int d = 1; d < 1024; d <<= 1) {
            int t = (tid >= d) ? sh[tid - d] : 0;
            __syncthreads();
            sh[tid] += t;
            __syncthreads();
        }
        int carry = carry_s;
        if (i < n) {
            int inc = carry + sh[tid];
            g_off[i + 1] = inc;
            g_cur[i] = inc - v;
        }
        __syncthreads();
        if (tid == 0) carry_s = carry + sh[1023];
        __syncthreads();
    }
}

__global__ void k_scatter(const int* __restrict__ ei, int E, int N) {
    int i = blockIdx.x * blockDim.x + threadIdx.x;
    if (i >= E + N) return;
    int src, dst;
    if (i < E) { src = ei[i]; dst = ei[E + i]; }
    else       { src = i - E; dst = i - E; }
    int slot = atomicAdd(&g_cur[dst], 1);
    g_csr[slot] = src;
}

// ---------------- layer1 aggregation: one warp per dst node ----------------
__global__ void k_agg1(const float* __restrict__ b1, int N) {
    int warp = (blockIdx.x * blockDim.x + threadIdx.x) >> 5;
    int lane = threadIdx.x & 31;
    if (warp >= N) return;
    int dst = warp;
    float ad[4];
#pragma unroll
    for (int h = 0; h < 4; h++) ad[h] = g_ad1[dst * 4 + h];
    int beg = g_off[dst], end = g_off[dst + 1];

    // pass 1: lane-parallel max of leaky(as[src]+ad) per head
    float m[4];
#pragma unroll
    for (int h = 0; h < 4; h++) m[h] = -CUDART_INF_F;
    for (int k = beg + lane; k < end; k += 32) {
        int src = g_csr[k];
#pragma unroll
        for (int h = 0; h < 4; h++) {
            float e = leaky(g_as1[src * 4 + h] + ad[h]);
            m[h] = fmaxf(m[h], e);
        }
    }
#pragma unroll
    for (int d = 16; d; d >>= 1)
#pragma unroll
        for (int h = 0; h < 4; h++)
            m[h] = fmaxf(m[h], __shfl_xor_sync(0xFFFFFFFFu, m[h], d));

    // pass 2: whole warp per edge, coalesced 1KB row of h1
    float s[4] = {0.f, 0.f, 0.f, 0.f};
    float acc[8] = {0.f, 0.f, 0.f, 0.f, 0.f, 0.f, 0.f, 0.f};
    for (int k = beg; k < end; k++) {
        int src = g_csr[k];
        float w[4];
#pragma unroll
        for (int h = 0; h < 4; h++) {
            float e = leaky(g_as1[src * 4 + h] + ad[h]);
            w[h] = __expf(e - m[h]);
            s[h] += w[h];
        }
        const float* hp = g_h1 + src * 256;
#pragma unroll
        for (int j = 0; j < 8; j++) {
            int c = lane + 32 * j;
            acc[j] = fmaf(w[c >> 6], hp[c], acc[j]);
        }
    }
#pragma unroll
    for (int j = 0; j < 8; j++) {
        int c = lane + 32 * j;
        float v = acc[j] / (s[c >> 6] + 1e-16f) + b1[c];
        g_out1[dst * 256 + c] = fmaxf(v, 0.f);
    }
}

// ---------------- layer2 GEMM + alpha: 8 warps/block, warp per node ----------------
__global__ void k_gemm2(const float* __restrict__ W2, const float* __restrict__ asrc2,
                        const float* __restrict__ adst2, int N) {
    __shared__ float sW[256 * 21];
    int tid = threadIdx.x;
    for (int i = tid; i < 256 * 21; i += 256) sW[i] = W2[i];
    __syncthreads();
    int warp = tid >> 5, lane = tid & 31;
    int n = blockIdx.x * 8 + warp;
    if (n >= N) return;
    float xr[8];
#pragma unroll
    for (int j = 0; j < 8; j++) xr[j] = g_out1[n * 256 + lane + 32 * j];
    float asum = 0.f, adsum = 0.f;
    for (int o = 0; o < 21; o++) {
        float p = 0.f;
#pragma unroll
        for (int j = 0; j < 8; j++) p = fmaf(xr[j], sW[(lane + 32 * j) * 21 + o], p);
#pragma unroll
        for (int d = 16; d; d >>= 1) p += __shfl_xor_sync(0xFFFFFFFFu, p, d);
        if (lane == 0) g_h2[n * 21 + o] = p;
        asum = fmaf(p, asrc2[o], asum);
        adsum = fmaf(p, adst2[o], adsum);
    }
    if (lane == 0) { g_as2[n] = asum; g_ad2[n] = adsum; }
}

// ---------------- layer2 aggregation + final row softmax: warp per node ----------------
__global__ void k_agg2(const float* __restrict__ b2, float* __restrict__ out, int N) {
    int warp = (blockIdx.x * blockDim.x + threadIdx.x) >> 5;
    int lane = threadIdx.x & 31;
    if (warp >= N) return;
    int dst = warp;
    float ad = g_ad2[dst];
    int beg = g_off[dst], end = g_off[dst + 1];

    float m = -CUDART_INF_F;
    for (int k = beg + lane; k < end; k += 32)
        m = fmaxf(m, leaky(g_as2[g_csr[k]] + ad));
#pragma unroll
    for (int d = 16; d; d >>= 1) m = fmaxf(m, __shfl_xor_sync(0xFFFFFFFFu, m, d));

    float s = 0.f, a = 0.f;
    for (int k = beg; k < end; k++) {
        int src = g_csr[k];
        float e = leaky(g_as2[src] + ad);
        float w = __expf(e - m);
        s += w;
        if (lane < 21) a = fmaf(w, g_h2[src * 21 + lane], a);
    }
    float v = (lane < 21) ? (a / (s + 1e-16f) + b2[lane]) : -CUDART_INF_F;

    // row softmax over 21 lanes
    float rm = v;
#pragma unroll
    for (int d = 16; d; d >>= 1) rm = fmaxf(rm, __shfl_xor_sync(0xFFFFFFFFu, rm, d));
    float ex = (lane < 21) ? __expf(v - rm) : 0.f;
    float ss = ex;
#pragma unroll
    for (int d = 16; d; d >>= 1) ss += __shfl_xor_sync(0xFFFFFFFFu, ss, d);
    if (lane < 21) out[dst * 21 + lane] = ex / ss;
}

// ---------------- launch ----------------
extern "C" void kernel_launch(void* const* d_in, const int* in_sizes, int n_in,
                              void* d_out, int out_size) {
    const float* x     = (const float*)d_in[0];
    const int*   ei    = (const int*)d_in[1];
    const float* W1    = (const float*)d_in[2];
    const float* asrc1 = (const float*)d_in[3];
    const float* adst1 = (const float*)d_in[4];
    const float* b1    = (const float*)d_in[5];
    const float* W2    = (const float*)d_in[6];
    const float* asrc2 = (const float*)d_in[7];
    const float* adst2 = (const float*)d_in[8];
    const float* b2    = (const float*)d_in[9];
    float* out = (float*)d_out;

    int N = in_sizes[0] / 3;
    int E = in_sizes[1] / 2;
    int T = E + N;

    k_gemm1<<<N, 256>>>(x, W1, asrc1, adst1, N);
    k_zero<<<(N + 255) / 256, 256>>>(N);
    k_count<<<(T + 255) / 256, 256>>>(ei, E, N);
    k_scan<<<1, 1024>>>(N);
    k_scatter<<<(T + 255) / 256, 256>>>(ei, E, N);
    k_agg1<<<(N + 7) / 8, 256>>>(b1, N);
    k_gemm2<<<(N + 7) / 8, 256>>>(W2, asrc2, adst2, N);
    k_agg2<<<(N + 7) / 8, 256>>>(b2, out, N);
}